// round 4
// baseline (speedup 1.0000x reference)
#include <cuda_runtime.h>
#include <math.h>

#define BATCH   4096
#define LIN     4448
#define LP      278      // after conv1(s4)+maxpool4: 1112/4
#define L2OUT   139      // conv2 output length
#define NQ      8
#define SD      256
#define NLAY    3

__device__ float g_feat[BATCH * SD];   // scratch: [B, 256] extractor features

// ---------- packed f32x2 helpers ----------
__device__ __forceinline__ unsigned long long splat2(float x) {
    unsigned long long r; unsigned u = __float_as_uint(x);
    asm("mov.b64 %0, {%1, %1};" : "=l"(r) : "r"(u));
    return r;
}
__device__ __forceinline__ unsigned long long fma2(unsigned long long a,
                                                   unsigned long long b,
                                                   unsigned long long c) {
    unsigned long long d;
    asm("fma.rn.f32x2 %0, %1, %2, %3;" : "=l"(d) : "l"(a), "l"(b), "l"(c));
    return d;
}
__device__ __forceinline__ float2 unpack2(unsigned long long v) {
    unsigned lo, hi;
    asm("mov.b64 {%0, %1}, %2;" : "=r"(lo), "=r"(hi) : "l"(v));
    return make_float2(__uint_as_float(lo), __uint_as_float(hi));
}

// ---------------- Kernel 1: conv stack (one sample per block) ----------------
#define SM_FLUX 0
#define SM_POOL (SM_FLUX + LIN)                 // [16][284] + 16 pad, +3 halo offset
#define SM_H2   (SM_POOL + 16*284 + 16)        // [32][141]
#define SM_W1P  (SM_H2 + 32*141)               // conv1 weight pairs [15][8] float2 = 240 f
#define SM_W2P  (SM_W1P + 240)                 // conv2 weight pairs [112][16] float2 = 3584 f
#define SM_BN1S (SM_W2P + 3584)
#define SM_BN1B (SM_BN1S + 16)
#define SM_BN2S (SM_BN1B + 16)
#define SM_BN2B (SM_BN2S + 32)
#define SM1_TOTAL (SM_BN2B + 32)               // 17440 floats = 69760 B

__global__ __launch_bounds__(256) void k_conv(
    const float* __restrict__ flux,
    const float* __restrict__ w1, const float* __restrict__ g1, const float* __restrict__ b1,
    const float* __restrict__ w2, const float* __restrict__ g2, const float* __restrict__ b2)
{
    extern __shared__ float sm[];
    const int tid = threadIdx.x;
    const int s = blockIdx.x;

    // stage flux row (coalesced float4)
    const float4* fx4 = (const float4*)(flux + (size_t)s * LIN);
    for (int i = tid; i < LIN/4; i += 256) ((float4*)(sm + SM_FLUX))[i] = fx4[i];

    // conv1 weight pairs: w1p[k][cp] = {w1[cp][k], w1[cp+8][k]}
    if (tid < 120) {
        int k = tid / 8, cp = tid % 8;
        sm[SM_W1P + (k*8 + cp)*2 + 0] = w1[cp*15 + k];
        sm[SM_W1P + (k*8 + cp)*2 + 1] = w1[(cp+8)*15 + k];
    }
    // conv2 weight pairs: w2p[ck][cp] = {w2[cp][ck], w2[cp+16][ck]}
    for (int i = tid; i < 112*16; i += 256) {
        int ck = i >> 4, cp = i & 15;
        sm[SM_W2P + i*2 + 0] = w2[cp*112 + ck];
        sm[SM_W2P + i*2 + 1] = w2[(cp+16)*112 + ck];
    }
    const float inv_eps = rsqrtf(1.0f + 1e-5f);
    if (tid < 16) { sm[SM_BN1S + tid] = g1[tid] * inv_eps; sm[SM_BN1B + tid] = b1[tid]; }
    if (tid < 32) { sm[SM_BN2S + tid] = g2[tid] * inv_eps; sm[SM_BN2B + tid] = b2[tid]; }
    for (int i = tid; i < 16*284 + 16; i += 256) sm[SM_POOL + i] = 0.f;
    __syncthreads();

    // conv1 (k=15,s=4,p=7) + BN + ReLU + MaxPool4, 2 channels packed per thread
    {
        const int cp = tid & 7, jb = tid >> 3;      // 8 channel-pairs x 32 pos-groups
        unsigned long long wp[15];
        #pragma unroll
        for (int k = 0; k < 15; k++)
            wp[k] = *(const unsigned long long*)&sm[SM_W1P + (k*8 + cp)*2];
        const float sc0 = sm[SM_BN1S + cp],     bt0 = sm[SM_BN1B + cp];
        const float sc1 = sm[SM_BN1S + cp + 8], bt1 = sm[SM_BN1B + cp + 8];
        for (int j = jb; j < LP; j += 32) {
            const int base = 16*j - 7;
            float f[27];
            if (j >= 1 && j <= 276) {
                #pragma unroll
                for (int t = 0; t < 27; t++) f[t] = sm[SM_FLUX + base + t];
            } else {
                #pragma unroll
                for (int t = 0; t < 27; t++) {
                    int xi = base + t;
                    f[t] = (xi >= 0 && xi < LIN) ? sm[SM_FLUX + xi] : 0.f;
                }
            }
            unsigned long long a0 = 0ull, a1 = 0ull, a2 = 0ull, a3 = 0ull;
            #pragma unroll
            for (int t = 0; t < 27; t++) {
                unsigned long long fs = splat2(f[t]);
                if (t < 15)            a0 = fma2(wp[t],    fs, a0);
                if (t >= 4 && t < 19)  a1 = fma2(wp[t-4],  fs, a1);
                if (t >= 8 && t < 23)  a2 = fma2(wp[t-8],  fs, a2);
                if (t >= 12)           a3 = fma2(wp[t-12], fs, a3);
            }
            float2 v0 = unpack2(a0), v1 = unpack2(a1), v2 = unpack2(a2), v3 = unpack2(a3);
            float mlo = fmaxf(fmaxf(v0.x, v1.x), fmaxf(v2.x, v3.x));
            float mhi = fmaxf(fmaxf(v0.y, v1.y), fmaxf(v2.y, v3.y));
            sm[SM_POOL + cp*284 + 3 + j]       = fmaxf(mlo*sc0 + bt0, 0.f);
            sm[SM_POOL + (cp+8)*284 + 3 + j]   = fmaxf(mhi*sc1 + bt1, 0.f);
        }
    }
    __syncthreads();

    // conv2 (16->32, k=7, s=2, p=3) + BN + ReLU
    // 2 channels packed x 9 consecutive positions per thread, single balanced sweep
    {
        const int cp = tid & 15, pg = tid >> 4;     // 16 channel-pairs x 16 pos-groups
        const float sc0 = sm[SM_BN2S + cp],      bt0 = sm[SM_BN2B + cp];
        const float sc1 = sm[SM_BN2S + cp + 16], bt1 = sm[SM_BN2B + cp + 16];
        const int p0 = pg * 9;                      // covers 0..143 >= 139
        unsigned long long acc[9];
        #pragma unroll
        for (int i = 0; i < 9; i++) acc[i] = 0ull;
        #pragma unroll
        for (int c = 0; c < 16; c++) {
            float f[23];                            // window for 9 stride-2 positions
            #pragma unroll
            for (int t = 0; t < 23; t++) {
                int xi = 2*p0 + t;
                f[t] = (xi < 284) ? sm[SM_POOL + c*284 + xi] : 0.f;
            }
            unsigned long long wp[7];
            #pragma unroll
            for (int k = 0; k < 7; k++)
                wp[k] = *(const unsigned long long*)&sm[SM_W2P + ((c*7 + k)*16 + cp)*2];
            #pragma unroll
            for (int i = 0; i < 9; i++) {
                #pragma unroll
                for (int k = 0; k < 7; k++) {
                    unsigned long long fs = splat2(f[2*i + k]);
                    acc[i] = fma2(wp[k], fs, acc[i]);
                }
            }
        }
        #pragma unroll
        for (int i = 0; i < 9; i++) {
            if (p0 + i < L2OUT) {
                float2 v = unpack2(acc[i]);
                sm[SM_H2 + cp*141 + p0 + i]      = fmaxf(v.x*sc0 + bt0, 0.f);
                sm[SM_H2 + (cp+16)*141 + p0 + i] = fmaxf(v.y*sc1 + bt1, 0.f);
            }
        }
    }
    __syncthreads();

    // adaptive_avg_pool1d(139 -> 8), feature layout c*8+i
    {
        const int c = tid >> 3, i = tid & 7;
        const int st = (i * L2OUT) >> 3;
        const int en = ((i + 1) * L2OUT + 7) >> 3;
        float acc = 0.f;
        for (int p = st; p < en; p++) acc += sm[SM_H2 + c*141 + p];
        g_feat[(size_t)s * SD + c*8 + i] = acc / (float)(en - st);
    }
}

// ---------------- Kernel 2: proj + normalize + VQC + head ----------------
// TB2=8 samples/block, 256 threads, ~11KB smem -> full occupancy, 512 blocks (1 wave)
#define TB2 8
#define S3_ROT 0                        // 24 gates x 8 entries (192 floats)
#define S3_Y   192                      // y1 [8][68] (16B-aligned rows)
#define S3_X   (S3_Y + 8*68)            // states [8][264] (16B-aligned rows)
#define SM3_TOTAL (S3_X + 8*264)        // 2848 floats = 11392 B

__global__ __launch_bounds__(256) void k_tail(
    const float* __restrict__ scalars,
    const float* __restrict__ W1, const float* __restrict__ B1,
    const float* __restrict__ W2, const float* __restrict__ B2,
    const float* __restrict__ qw,
    const float* __restrict__ hw1, const float* __restrict__ hb1,
    const float* __restrict__ hg,  const float* __restrict__ hbb,
    const float* __restrict__ hw2, const float* __restrict__ hb2,
    float* __restrict__ out)
{
    extern __shared__ float sm[];
    const int tid = threadIdx.x;
    const int s0 = blockIdx.x * TB2;

    // precompute the 24 Rot matrices once per block
    if (tid < NLAY*NQ) {
        float phi = __ldg(qw + tid*3 + 0);
        float th  = __ldg(qw + tid*3 + 1);
        float om  = __ldg(qw + tid*3 + 2);
        float sh, ch; sincosf(0.5f*th, &sh, &ch);
        float sa, ca; sincosf(0.5f*(phi + om), &sa, &ca);
        float sb, cb; sincosf(0.5f*(phi - om), &sb, &cb);
        float* u = sm + S3_ROT + tid*8;
        u[0] =  ca*ch;  u[1] = -sa*ch;    // u00
        u[2] = -cb*sh;  u[3] = -sb*sh;    // u01
        u[4] =  cb*sh;  u[5] = -sb*sh;    // u10
        u[6] =  ca*ch;  u[7] =  sa*ch;    // u11
    }

    // proj1: y1[s][j] = relu(b1[j] + feat[s]·W1[j]); thread = (j, 2-sample group)
    {
        const int j = tid >> 2, sg = tid & 3;
        const float4* w4 = (const float4*)(W1 + j*256);
        const float4* f0 = (const float4*)(g_feat + (size_t)(s0 + sg*2)*SD);
        const float4* f1 = (const float4*)(g_feat + (size_t)(s0 + sg*2 + 1)*SD);
        float acc0 = __ldg(B1 + j), acc1 = acc0;
        #pragma unroll 8
        for (int k4 = 0; k4 < 64; k4++) {
            float4 w = __ldg(w4 + k4);
            float4 a = __ldg(f0 + k4);
            float4 b = __ldg(f1 + k4);
            acc0 += w.x*a.x + w.y*a.y + w.z*a.z + w.w*a.w;
            acc1 += w.x*b.x + w.y*b.y + w.z*b.z + w.w*b.w;
        }
        sm[S3_Y + (sg*2 + 0)*68 + j] = fmaxf(acc0, 0.f);
        sm[S3_Y + (sg*2 + 1)*68 + j] = fmaxf(acc1, 0.f);
    }
    __syncthreads();

    // proj2: x[s][m] = b2[m] + y1[s]·W2[m]; thread = m, all 8 samples
    {
        const int m = tid;
        const float4* w4 = (const float4*)(W2 + m*64);
        float acc[TB2];
        const float bb = __ldg(B2 + m);
        #pragma unroll
        for (int si = 0; si < TB2; si++) acc[si] = bb;
        #pragma unroll 4
        for (int j4 = 0; j4 < 16; j4++) {
            float4 w = __ldg(w4 + j4);
            #pragma unroll
            for (int si = 0; si < TB2; si++) {
                float4 y = *(const float4*)&sm[S3_Y + si*68 + j4*4];
                acc[si] += w.x*y.x + w.y*y.y + w.z*y.z + w.w*y.w;
            }
        }
        #pragma unroll
        for (int si = 0; si < TB2; si++) sm[S3_X + si*264 + m] = acc[si];
    }
    __syncthreads();

    // one warp per sample: normalize + 8-qubit/3-layer circuit in registers + head
    const int warp = tid >> 5, lane = tid & 31;
    const unsigned FULL = 0xffffffffu;
    {
        const int sl = warp;
        const int gs = s0 + sl;
        float are[8], aim[8];
        {
            float4 v0 = *(const float4*)&sm[S3_X + sl*264 + lane*8];
            float4 v1 = *(const float4*)&sm[S3_X + sl*264 + lane*8 + 4];
            are[0] = v0.x; are[1] = v0.y; are[2] = v0.z; are[3] = v0.w;
            are[4] = v1.x; are[5] = v1.y; are[6] = v1.z; are[7] = v1.w;
        }
        float sq = 0.f;
        #pragma unroll
        for (int m = 0; m < 8; m++) { aim[m] = 0.f; sq += are[m]*are[m]; }
        #pragma unroll
        for (int off = 16; off; off >>= 1) sq += __shfl_xor_sync(FULL, sq, off);
        float n   = sqrtf(sq);
        float inv = 1.0f / fmaxf(n, 1e-12f);
        if (n * inv < 1e-8f) {
            #pragma unroll
            for (int m = 0; m < 8; m++) are[m] = 0.0625f;   // 1/sqrt(256)
        } else {
            #pragma unroll
            for (int m = 0; m < 8; m++) are[m] *= inv;
        }

        for (int l = 0; l < NLAY; l++) {
            for (int q = 0; q < NQ; q++) {
                const float* u = sm + S3_ROT + (l*NQ + q)*8;
                int b = 7 - q;
                if (b >= 3) {                       // lane-bit gate, SEL-free inner loop
                    int lb = b - 3;
                    unsigned msk = 1u << lb;
                    bool hi = (lane >> lb) & 1;
                    float cmr = hi ? u[6] : u[0];   // coeff of my amplitude
                    float cmi = hi ? u[7] : u[1];
                    float cpr = hi ? u[4] : u[2];   // coeff of partner amplitude
                    float cpi = hi ? u[5] : u[3];
                    #pragma unroll
                    for (int m = 0; m < 8; m++) {
                        float pr = __shfl_xor_sync(FULL, are[m], msk);
                        float pi = __shfl_xor_sync(FULL, aim[m], msk);
                        float mr = are[m], mi = aim[m];
                        are[m] = cmr*mr - cmi*mi + cpr*pr - cpi*pi;
                        aim[m] = cmr*mi + cmi*mr + cpr*pi + cpi*pr;
                    }
                } else {                            // register-local gate
                    float u00r = u[0], u00i = u[1], u01r = u[2], u01i = u[3];
                    float u10r = u[4], u10i = u[5], u11r = u[6], u11i = u[7];
                    int mb = 1 << b;
                    #pragma unroll
                    for (int m0 = 0; m0 < 8; m0++) {
                        if (m0 & mb) continue;
                        int m1 = m0 | mb;
                        float a0r = are[m0], a0i = aim[m0];
                        float a1r = are[m1], a1i = aim[m1];
                        are[m0] = u00r*a0r - u00i*a0i + u01r*a1r - u01i*a1i;
                        aim[m0] = u00r*a0i + u00i*a0r + u01r*a1i + u01i*a1r;
                        are[m1] = u10r*a0r - u10i*a0i + u11r*a1r - u11i*a1i;
                        aim[m1] = u10r*a0i + u10i*a0r + u11r*a1i + u11i*a1r;
                    }
                }
            }
            // CNOT ring: (0,1)(1,2)...(7,0); wire q <-> state bit 7-q
            #pragma unroll
            for (int q = 0; q < 4; q++) {           // both bits in lane
                unsigned shm  = 1u << (3 - q);
                unsigned cond = 1u << (4 - q);
                bool take = (lane & cond) != 0;
                #pragma unroll
                for (int m = 0; m < 8; m++) {
                    float pr = __shfl_xor_sync(FULL, are[m], shm);
                    float pi = __shfl_xor_sync(FULL, aim[m], shm);
                    if (take) { are[m] = pr; aim[m] = pi; }
                }
            }
            if (lane & 1) {                         // CNOT(4,5): ctrl lane bit0, tgt m bit2
                #pragma unroll
                for (int m = 0; m < 4; m++) {
                    float tr = are[m]; are[m] = are[m+4]; are[m+4] = tr;
                    float ti = aim[m]; aim[m] = aim[m+4]; aim[m+4] = ti;
                }
            }
            {   // CNOT(5,6): swap (4,6),(5,7); CNOT(6,7): swap (2,3),(6,7)
                float t;
                t = are[4]; are[4] = are[6]; are[6] = t;  t = aim[4]; aim[4] = aim[6]; aim[6] = t;
                t = are[5]; are[5] = are[7]; are[7] = t;  t = aim[5]; aim[5] = aim[7]; aim[7] = t;
                t = are[2]; are[2] = are[3]; are[3] = t;  t = aim[2]; aim[2] = aim[3]; aim[3] = t;
                t = are[6]; are[6] = are[7]; are[7] = t;  t = aim[6]; aim[6] = aim[7]; aim[7] = t;
            }
            #pragma unroll
            for (int m = 1; m < 8; m += 2) {        // CNOT(7,0): ctrl m bit0, tgt lane bit4
                are[m] = __shfl_xor_sync(FULL, are[m], 16);
                aim[m] = __shfl_xor_sync(FULL, aim[m], 16);
            }
        }

        // <Z_q> expectations
        float S = 0.f, S5 = 0.f, S6 = 0.f, S7 = 0.f;
        #pragma unroll
        for (int m = 0; m < 8; m++) {
            float p = are[m]*are[m] + aim[m]*aim[m];
            S  += p;
            S5 += (m & 4) ? -p : p;
            S6 += (m & 2) ? -p : p;
            S7 += (m & 1) ? -p : p;
        }
        float z[8];
        z[0] = (lane & 16) ? -S : S;
        z[1] = (lane &  8) ? -S : S;
        z[2] = (lane &  4) ? -S : S;
        z[3] = (lane &  2) ? -S : S;
        z[4] = (lane &  1) ? -S : S;
        z[5] = S5; z[6] = S6; z[7] = S7;
        #pragma unroll
        for (int q = 0; q < 8; q++)
            #pragma unroll
            for (int off = 16; off; off >>= 1)
                z[q] += __shfl_xor_sync(FULL, z[q], off);

        // head: [z(8), scalars(6)] -> 32 (BN eval + relu) -> 3
        float in[14];
        #pragma unroll
        for (int k = 0; k < 8; k++) in[k] = z[k];
        #pragma unroll
        for (int k = 0; k < 6; k++) in[8 + k] = __ldg(scalars + (size_t)gs*6 + k);
        float acc = __ldg(hb1 + lane);
        #pragma unroll
        for (int k = 0; k < 14; k++) acc += in[k] * __ldg(hw1 + lane*14 + k);
        float bsc = __ldg(hg + lane) * rsqrtf(1.0f + 1e-5f);
        float h = fmaxf(acc*bsc + __ldg(hbb + lane), 0.f);
        #pragma unroll
        for (int o = 0; o < 3; o++) {
            float v = h * __ldg(hw2 + o*32 + lane);
            #pragma unroll
            for (int off = 16; off; off >>= 1) v += __shfl_xor_sync(FULL, v, off);
            if (lane == o) out[(size_t)gs*3 + o] = v + __ldg(hb2 + o);
        }
    }
}

extern "C" void kernel_launch(void* const* d_in, const int* in_sizes, int n_in,
                              void* d_out, int out_size)
{
    const float* flux    = (const float*)d_in[0];
    const float* scalars = (const float*)d_in[1];
    const float* conv1_w = (const float*)d_in[2];
    const float* bn1_g   = (const float*)d_in[3];
    const float* bn1_b   = (const float*)d_in[4];
    const float* conv2_w = (const float*)d_in[5];
    const float* bn2_g   = (const float*)d_in[6];
    const float* bn2_b   = (const float*)d_in[7];
    const float* proj_w1 = (const float*)d_in[8];
    const float* proj_b1 = (const float*)d_in[9];
    const float* proj_w2 = (const float*)d_in[10];
    const float* proj_b2 = (const float*)d_in[11];
    const float* q_w     = (const float*)d_in[12];
    const float* head_w1 = (const float*)d_in[13];
    const float* head_b1 = (const float*)d_in[14];
    const float* head_g  = (const float*)d_in[15];
    const float* head_bb = (const float*)d_in[16];
    const float* head_w2 = (const float*)d_in[17];
    const float* head_b2 = (const float*)d_in[18];
    float* out = (float*)d_out;

    int B = in_sizes[1] / 6;           // scalars [B,6]
    if (B > BATCH) B = BATCH;

    cudaFuncSetAttribute(k_conv, cudaFuncAttributeMaxDynamicSharedMemorySize, SM1_TOTAL*4);
    cudaFuncSetAttribute(k_tail, cudaFuncAttributeMaxDynamicSharedMemorySize, SM3_TOTAL*4);

    k_conv<<<B, 256, SM1_TOTAL*4>>>(flux, conv1_w, bn1_g, bn1_b, conv2_w, bn2_g, bn2_b);
    k_tail<<<B/TB2, 256, SM3_TOTAL*4>>>(scalars, proj_w1, proj_b1, proj_w2, proj_b2,
                                        q_w, head_w1, head_b1, head_g, head_bb,
                                        head_w2, head_b2, out);
}